// round 4
// baseline (speedup 1.0000x reference)
#include <cuda_runtime.h>
#include <math.h>
#include <float.h>

#define B 8
#define SEQ 12
#define NN 1000
#define E 16000
#define HID 128
#define HEADS 8
#define DH 16
#define M_ROWS (B*NN)          /* 8000 */

typedef unsigned long long ull;

// ---------------- f32x2 packed helpers (FFMA2 — ptxas never emits this itself) ----
__device__ __forceinline__ ull pack2(float x, float y){
    ull r; asm("mov.b64 %0, {%1, %2};" : "=l"(r) : "f"(x), "f"(y)); return r;
}
__device__ __forceinline__ void fma2(ull& d, ull a, ull b){
    asm("fma.rn.f32x2 %0, %1, %2, %0;" : "+l"(d) : "l"(a), "l"(b));
}
__device__ __forceinline__ float2 unpack2(ull v){
    float2 r; asm("mov.b64 {%0, %1}, %2;" : "=f"(r.x), "=f"(r.y) : "l"(v)); return r;
}

// ---------------- static device scratch ----------------
__device__ float g_hin[(size_t)SEQ*B*NN*HID];   // [SEQ][B][N][HID]
__device__ float g_y  [(size_t)M_ROWS*HID];
__device__ float g_hp [(size_t)M_ROWS*HID];
__device__ float g_k1 [(size_t)M_ROWS*HID];
__device__ float g_k2 [(size_t)M_ROWS*HID];
__device__ float g_k3 [(size_t)M_ROWS*HID];
__device__ float g_tmp[(size_t)M_ROWS*HID];
__device__ float g_el [(size_t)M_ROWS*HEADS];
__device__ float g_er [(size_t)M_ROWS*HEADS];
__device__ int   g_cnt[NN];
__device__ int   g_cur[NN];
__device__ int   g_off[NN+1];
__device__ int   g_eidx[E];

// ---------------- fused init: inproj + y=h[:,0] + CSR zero ----------------
__global__ void k_init(const float* __restrict__ inp, const float* __restrict__ w_in,
                       const float* __restrict__ b_in, float* __restrict__ hin,
                       float* __restrict__ y, int* cnt, int* cur){
    int row = blockIdx.x;                 // over B*SEQ*NN (input order [B][SEQ][N])
    int t = threadIdx.x;
    if (blockIdx.x < 8){
        int q = blockIdx.x*128 + t;
        if (q < NN){ cnt[q] = 0; cur[q] = 0; }
    }
    int b = row / (SEQ*NN);
    int s = (row / NN) % SEQ;
    int n = row % NN;
    float x0 = inp[(size_t)row*2 + 0];
    float x1 = inp[(size_t)row*2 + 1];
    float v = fmaf(x0, w_in[t], fmaf(x1, w_in[HID+t], b_in[t]));
    hin[(((size_t)s*B + b)*NN + n)*HID + t] = v;
    if (s == 0) y[((size_t)b*NN + n)*HID + t] = v;
}

// ---------------- CSR construction (deterministic: per-node sorted edge ids) ----
__global__ void k_csr_count(const int* __restrict__ dst, int* cnt){
    int e = blockIdx.x*blockDim.x + threadIdx.x;
    if (e < E) atomicAdd(&cnt[dst[e]], 1);
}
__global__ void k_csr_scan(const int* __restrict__ cnt, int* off){
    __shared__ int s[1024];
    int t = threadIdx.x;
    s[t] = (t < NN) ? cnt[t] : 0;
    __syncthreads();
    #pragma unroll
    for (int o = 1; o < 1024; o <<= 1){
        int v = (t >= o) ? s[t-o] : 0;
        __syncthreads();
        s[t] += v;
        __syncthreads();
    }
    if (t == 0) off[0] = 0;
    if (t < NN) off[t+1] = s[t];
}
__global__ void k_csr_fill(const int* __restrict__ dst, const int* __restrict__ off,
                           int* cur, int* eidx){
    int e = blockIdx.x*blockDim.x + threadIdx.x;
    if (e < E){
        int d = dst[e];
        int p = atomicAdd(&cur[d], 1);
        eidx[off[d] + p] = e;
    }
}
__global__ void k_csr_sort(const int* __restrict__ off, int* eidx){
    if (threadIdx.x != 0) return;
    int n = blockIdx.x;
    int a = off[n], b = off[n+1];
    for (int i = a+1; i < b; i++){
        int v = eidx[i]; int j = i-1;
        while (j >= a && eidx[j] > v){ eidx[j+1] = eidx[j]; j--; }
        eidx[j+1] = v;
    }
}

// ---------------- GEMM (f32x2): C = act( (A0 + c1*A1)@W0 [+ A2@W1] + b0 + b1 ) ----
// 64 rows x 128 cols per block, 125 blocks (single wave), 256 threads.
// tx = lane (0..31) -> 4 cols (= 2 f32x2); ty = warp (0..7) -> 8 rows.
// A tile staged in dynamic smem PRE-DUPLICATED as (a,a) f32x2 pairs.
// Optional epilogue: el/er per-(row,head) GAT logits.
extern __shared__ float2 sA2[];   // 64 * 128 float2 = 64KB

__global__ void __launch_bounds__(256) k_gemm(
    const float* __restrict__ A0, const float* __restrict__ A1, float c1,
    const float* __restrict__ W0,
    const float* __restrict__ A2, const float* __restrict__ W1,
    const float* __restrict__ b0, const float* __restrict__ b1,
    float* __restrict__ C, int act,
    float* __restrict__ el, float* __restrict__ er,
    const float* __restrict__ a_l, const float* __restrict__ a_r)
{
    int row0 = blockIdx.x * 64;
    int tid = threadIdx.x;
    int tx = tid & 31, ty = tid >> 5;       // lane / warp
    int col0 = tx * 4;

    ull acc[8][2];
    #pragma unroll
    for (int i=0;i<8;i++){ acc[i][0] = 0ull; acc[i][1] = 0ull; }

    // ---- stage A tile (fused axpy), duplicated pairs ----
    {
        const float4* A04 = (const float4*)A0;
        const float4* A14 = (const float4*)A1;
        for (int i = tid; i < 64*32; i += 256){
            int r = i >> 5, c4 = i & 31;
            float4 v = A04[(size_t)(row0+r)*32 + c4];
            if (A1){
                float4 u = A14[(size_t)(row0+r)*32 + c4];
                v.x = fmaf(c1,u.x,v.x); v.y = fmaf(c1,u.y,v.y);
                v.z = fmaf(c1,u.z,v.z); v.w = fmaf(c1,u.w,v.w);
            }
            float2* p = &sA2[r*HID + c4*4];
            p[0] = make_float2(v.x,v.x); p[1] = make_float2(v.y,v.y);
            p[2] = make_float2(v.z,v.z); p[3] = make_float2(v.w,v.w);
        }
    }
    __syncthreads();
    // ---- product 0 ----
    {
        const float4* W4 = (const float4*)W0;
        const ull* sArow = (const ull*)(sA2 + ty*8*HID);
        #pragma unroll 2
        for (int k = 0; k < HID; k++){
            float4 wv = __ldg(&W4[(size_t)k*32 + tx]);
            ull w01 = pack2(wv.x, wv.y);
            ull w23 = pack2(wv.z, wv.w);
            #pragma unroll
            for (int i=0;i<8;i++){
                ull a2 = sArow[i*HID + k];
                fma2(acc[i][0], a2, w01);
                fma2(acc[i][1], a2, w23);
            }
        }
    }
    // ---- optional product 1 ----
    if (A2){
        __syncthreads();
        const float4* A24 = (const float4*)A2;
        for (int i = tid; i < 64*32; i += 256){
            int r = i >> 5, c4 = i & 31;
            float4 v = A24[(size_t)(row0+r)*32 + c4];
            float2* p = &sA2[r*HID + c4*4];
            p[0] = make_float2(v.x,v.x); p[1] = make_float2(v.y,v.y);
            p[2] = make_float2(v.z,v.z); p[3] = make_float2(v.w,v.w);
        }
        __syncthreads();
        const float4* W4 = (const float4*)W1;
        const ull* sArow = (const ull*)(sA2 + ty*8*HID);
        #pragma unroll 2
        for (int k = 0; k < HID; k++){
            float4 wv = __ldg(&W4[(size_t)k*32 + tx]);
            ull w01 = pack2(wv.x, wv.y);
            ull w23 = pack2(wv.z, wv.w);
            #pragma unroll
            for (int i=0;i<8;i++){
                ull a2 = sArow[i*HID + k];
                fma2(acc[i][0], a2, w01);
                fma2(acc[i][1], a2, w23);
            }
        }
    }
    // ---- unpack + bias ----
    float cf[8][4];
    float bias[4] = {0.f,0.f,0.f,0.f};
    if (b0){
        #pragma unroll
        for (int j=0;j<4;j++) bias[j] += b0[col0+j];
    }
    if (b1){
        #pragma unroll
        for (int j=0;j<4;j++) bias[j] += b1[col0+j];
    }
    #pragma unroll
    for (int i=0;i<8;i++){
        float2 p0 = unpack2(acc[i][0]);
        float2 p1 = unpack2(acc[i][1]);
        cf[i][0] = p0.x + bias[0]; cf[i][1] = p0.y + bias[1];
        cf[i][2] = p1.x + bias[2]; cf[i][3] = p1.y + bias[3];
    }
    // ---- store (with optional tanh) ----
    #pragma unroll
    for (int i=0;i<8;i++){
        int r = row0 + ty*8 + i;
        float4 o;
        o.x = cf[i][0]; o.y = cf[i][1]; o.z = cf[i][2]; o.w = cf[i][3];
        if (act){ o.x=tanhf(o.x); o.y=tanhf(o.y); o.z=tanhf(o.z); o.w=tanhf(o.w); }
        *reinterpret_cast<float4*>(C + (size_t)r*HID + col0) = o;
    }
    // ---- GAT logit epilogue: el/er[row][head]; head = tx>>2 (4 cols per head) ----
    if (el){
        int head  = tx >> 2;
        int dbase = (tx & 3) * 4;
        #pragma unroll
        for (int i=0;i<8;i++){
            float pl = 0.f, pr = 0.f;
            #pragma unroll
            for (int j=0;j<4;j++){
                pl = fmaf(cf[i][j], a_l[head*DH + dbase + j], pl);
                pr = fmaf(cf[i][j], a_r[head*DH + dbase + j], pr);
            }
            pl += __shfl_xor_sync(0xffffffffu, pl, 1);
            pl += __shfl_xor_sync(0xffffffffu, pl, 2);
            pr += __shfl_xor_sync(0xffffffffu, pr, 1);
            pr += __shfl_xor_sync(0xffffffffu, pr, 2);
            if ((tx & 3) == 0){
                int r = row0 + ty*8 + i;
                el[(size_t)r*HEADS + head] = pl;
                er[(size_t)r*HEADS + head] = pr;
            }
        }
    }
}

// ---------------- GAT: warp-per-(node,batch); no block barriers ----------------
// grid = NN blocks, 256 threads: warp w = batch w, all 8 batches of node blockIdx.x.
// lane handles dims {lane, lane+32, lane+64, lane+96}; head(dim)=dim>>4.
__global__ void __launch_bounds__(256) k_gat(
    const float* __restrict__ hp, const float* __restrict__ el,
    const float* __restrict__ er,
    const int* __restrict__ off, const int* __restrict__ eidx,
    const int* __restrict__ src, float* __restrict__ kout,
    const float* __restrict__ yin, const float* __restrict__ k1,
    const float* __restrict__ k2, const float* __restrict__ k3, float dtc)
{
    const unsigned FULL = 0xffffffffu;
    int n    = blockIdx.x;
    int b    = threadIdx.x >> 5;
    int lane = threadIdx.x & 31;
    int bn   = b*NN + n;

    const float* hb  = hp + (size_t)b*NN*HID;
    const float* elb = el + (size_t)b*NN*HEADS;

    // er for this destination node (all heads; broadcast 32B load)
    float erv[8];
    {
        float4 e0v = *reinterpret_cast<const float4*>(er + (size_t)bn*HEADS);
        float4 e1v = *reinterpret_cast<const float4*>(er + (size_t)bn*HEADS + 4);
        erv[0]=e0v.x; erv[1]=e0v.y; erv[2]=e0v.z; erv[3]=e0v.w;
        erv[4]=e1v.x; erv[5]=e1v.y; erv[6]=e1v.z; erv[7]=e1v.w;
    }

    int e0 = off[n], deg = off[n+1] - e0;

    float acc[4] = {0.f,0.f,0.f,0.f};
    float m[8], ssum[8];
    #pragma unroll
    for (int h=0;h<8;h++){ m[h] = -FLT_MAX; ssum[h] = 0.f; }

    for (int base = 0; base < deg; base += 32){
        int cnt = min(32, deg - base);
        int sj = 0;
        float lg[8];
        if (lane < cnt){
            sj = src[eidx[e0 + base + lane]];
            float4 v0 = *reinterpret_cast<const float4*>(elb + (size_t)sj*HEADS);
            float4 v1 = *reinterpret_cast<const float4*>(elb + (size_t)sj*HEADS + 4);
            float t0;
            t0 = v0.x + erv[0]; lg[0] = (t0>=0.f)?t0:0.2f*t0;
            t0 = v0.y + erv[1]; lg[1] = (t0>=0.f)?t0:0.2f*t0;
            t0 = v0.z + erv[2]; lg[2] = (t0>=0.f)?t0:0.2f*t0;
            t0 = v0.w + erv[3]; lg[3] = (t0>=0.f)?t0:0.2f*t0;
            t0 = v1.x + erv[4]; lg[4] = (t0>=0.f)?t0:0.2f*t0;
            t0 = v1.y + erv[5]; lg[5] = (t0>=0.f)?t0:0.2f*t0;
            t0 = v1.z + erv[6]; lg[6] = (t0>=0.f)?t0:0.2f*t0;
            t0 = v1.w + erv[7]; lg[7] = (t0>=0.f)?t0:0.2f*t0;
        } else {
            #pragma unroll
            for (int h=0;h<8;h++) lg[h] = -FLT_MAX;
        }
        // warp max per head
        float nm[8];
        #pragma unroll
        for (int h=0;h<8;h++) nm[h] = lg[h];
        #pragma unroll
        for (int o = 16; o > 0; o >>= 1){
            #pragma unroll
            for (int h=0;h<8;h++)
                nm[h] = fmaxf(nm[h], __shfl_xor_sync(FULL, nm[h], o));
        }
        // online-softmax merge
        float w[8], sc[8];
        #pragma unroll
        for (int h=0;h<8;h++){
            float newm = fmaxf(m[h], nm[h]);
            sc[h] = (m[h] == -FLT_MAX) ? 0.f : __expf(m[h] - newm);
            m[h]  = newm;
            w[h]  = __expf(lg[h] - newm);     // 0 for invalid lanes
        }
        if (base > 0){
            #pragma unroll
            for (int g=0;g<4;g++){
                float s01 = (lane < 16) ? sc[2*g] : sc[2*g+1];
                acc[g] *= s01;
            }
            #pragma unroll
            for (int h=0;h<8;h++) ssum[h] *= sc[h];
        }
        // chunk weight sums
        float cs[8];
        #pragma unroll
        for (int h=0;h<8;h++) cs[h] = w[h];
        #pragma unroll
        for (int o = 16; o > 0; o >>= 1){
            #pragma unroll
            for (int h=0;h<8;h++)
                cs[h] += __shfl_xor_sync(FULL, cs[h], o);
        }
        #pragma unroll
        for (int h=0;h<8;h++) ssum[h] += cs[h];
        // aggregation
        for (int j = 0; j < cnt; j++){
            int s = __shfl_sync(FULL, sj, j);
            const float* hr = hb + (size_t)s*HID;
            #pragma unroll
            for (int g=0;g<4;g++){
                float wa = __shfl_sync(FULL, w[2*g],   j);
                float wb = __shfl_sync(FULL, w[2*g+1], j);
                float ww = (lane < 16) ? wa : wb;
                acc[g] = fmaf(ww, hr[lane + 32*g], acc[g]);
            }
        }
    }
    #pragma unroll
    for (int g=0;g<4;g++){
        float s = ((lane < 16) ? ssum[2*g] : ssum[2*g+1]) + 1e-16f;
        float kv = acc[g] / s;
        size_t o = (size_t)bn*HID + lane + 32*g;
        if (yin){
            kout[o] = yin[o] + dtc*(k1[o] + 2.f*k2[o] + 2.f*k3[o] + kv);
        } else {
            kout[o] = kv;
        }
    }
}

// ---------------- LayerNorm over last dim (128) ----------------
__global__ void __launch_bounds__(128) k_ln(const float* __restrict__ s, float* __restrict__ d){
    int row = blockIdx.x;
    int t = threadIdx.x;
    __shared__ float sh[4];
    float v = s[(size_t)row*HID + t];

    float a = v;
    #pragma unroll
    for (int o = 16; o > 0; o >>= 1) a += __shfl_xor_sync(0xffffffffu, a, o);
    if ((t & 31) == 0) sh[t >> 5] = a;
    __syncthreads();
    float mean = (sh[0]+sh[1]+sh[2]+sh[3]) * (1.f/HID);

    float dv = v - mean;
    float q = dv*dv;
    __syncthreads();
    #pragma unroll
    for (int o = 16; o > 0; o >>= 1) q += __shfl_xor_sync(0xffffffffu, q, o);
    if ((t & 31) == 0) sh[t >> 5] = q;
    __syncthreads();
    float var = (sh[0]+sh[1]+sh[2]+sh[3]) * (1.f/HID);

    d[(size_t)row*HID + t] = dv / sqrtf(var + 1e-5f);
}

// ---------------- launch ----------------
extern "C" void kernel_launch(void* const* d_in, const int* in_sizes, int n_in,
                              void* d_out, int out_size)
{
    const float* inputs = (const float*)d_in[0];
    const int*   src    = (const int*)  d_in[1];
    const int*   dst    = (const int*)  d_in[2];
    const float* w_in   = (const float*)d_in[3];
    const float* b_in   = (const float*)d_in[4];
    const float* w_gat  = (const float*)d_in[5];
    const float* a_l    = (const float*)d_in[6];
    const float* a_r    = (const float*)d_in[7];
    const float* w_W    = (const float*)d_in[8];
    const float* b_W    = (const float*)d_in[9];
    const float* w_U    = (const float*)d_in[10];
    const float* b_U    = (const float*)d_in[11];
    const float* w_o1   = (const float*)d_in[12];
    const float* b_o1   = (const float*)d_in[13];
    const float* w_o2   = (const float*)d_in[14];
    const float* b_o2   = (const float*)d_in[15];
    float* out = (float*)d_out;

    float *hin, *y, *hp, *k1, *k2, *k3, *tmp, *el, *er;
    int *cnt, *cur, *off, *eidx;
    cudaGetSymbolAddress((void**)&hin, g_hin);
    cudaGetSymbolAddress((void**)&y,   g_y);
    cudaGetSymbolAddress((void**)&hp,  g_hp);
    cudaGetSymbolAddress((void**)&k1,  g_k1);
    cudaGetSymbolAddress((void**)&k2,  g_k2);
    cudaGetSymbolAddress((void**)&k3,  g_k3);
    cudaGetSymbolAddress((void**)&tmp, g_tmp);
    cudaGetSymbolAddress((void**)&el,  g_el);
    cudaGetSymbolAddress((void**)&er,  g_er);
    cudaGetSymbolAddress((void**)&cnt, g_cnt);
    cudaGetSymbolAddress((void**)&cur, g_cur);
    cudaGetSymbolAddress((void**)&off, g_off);
    cudaGetSymbolAddress((void**)&eidx,g_eidx);

    const float* F0 = (const float*)0;
    float*       FW = (float*)0;

    static bool attr_set = false;
    if (!attr_set){
        cudaFuncSetAttribute(k_gemm, cudaFuncAttributeMaxDynamicSharedMemorySize, 65536);
        attr_set = true;
    }
    const int SMEM = 64*HID*sizeof(float2);   // 64KB

    // prelude: k_gemm#1 sits at launch position 4 for ncu capture
    k_init     <<<B*SEQ*NN, HID>>>(inputs, w_in, b_in, hin, y, cnt, cur);
    k_csr_count<<<(E+255)/256, 256>>>(dst, cnt);
    k_csr_scan <<<1, 1024>>>(cnt, off);

    const float dt  = 0.25f;
    const float dtc = dt / 6.0f;

    // first RK4 stage-1 GEMM (does not need CSR)
    k_gemm<<<125,256,SMEM>>>(y, F0, 0.f, w_gat, F0,F0,F0,F0, hp, 0, el, er, a_l, a_r);

    k_csr_fill <<<(E+255)/256, 256>>>(dst, off, cur, eidx);
    k_csr_sort <<<NN, 32>>>(off, eidx);

    for (int idx = 0; idx < SEQ; idx++){
        for (int s = 0; s < 4; s++){
            if (!(idx == 0 && s == 0)){
                k_gemm<<<125,256,SMEM>>>(y, F0, 0.f, w_gat, F0,F0,F0,F0, hp, 0, el, er, a_l, a_r);
            }
            k_gat <<<NN,256>>>(hp, el, er, off, eidx, src, k1, F0,F0,F0,F0, 0.f);
            k_gemm<<<125,256,SMEM>>>(y, k1, 0.5f*dt, w_gat, F0,F0,F0,F0, hp, 0, el, er, a_l, a_r);
            k_gat <<<NN,256>>>(hp, el, er, off, eidx, src, k2, F0,F0,F0,F0, 0.f);
            k_gemm<<<125,256,SMEM>>>(y, k2, 0.5f*dt, w_gat, F0,F0,F0,F0, hp, 0, el, er, a_l, a_r);
            k_gat <<<NN,256>>>(hp, el, er, off, eidx, src, k3, F0,F0,F0,F0, 0.f);
            k_gemm<<<125,256,SMEM>>>(y, k3, dt, w_gat, F0,F0,F0,F0, hp, 0, el, er, a_l, a_r);
            k_gat <<<NN,256>>>(hp, el, er, off, eidx, src, y, y, k1, k2, k3, dtc);
        }
        if (idx > 0){
            const float* hidx = hin + (size_t)idx * M_ROWS * HID;
            k_gemm<<<125,256,SMEM>>>(y, F0, 0.f, w_W, hidx, w_U, b_W, b_U, tmp, 1, FW,FW,F0,F0);
            k_ln  <<<M_ROWS,128>>>(tmp, y);
        } else {
            k_ln  <<<M_ROWS,128>>>(y, y);
        }
    }

    // out = tanh(y@w_o1 + b_o1) @ w_o2 + b_o2
    k_gemm<<<125,256,SMEM>>>(y,   F0, 0.f, w_o1, F0,F0, b_o1,F0, tmp, 1, FW,FW,F0,F0);
    k_gemm<<<125,256,SMEM>>>(tmp, F0, 0.f, w_o2, F0,F0, b_o2,F0, out, 0, FW,FW,F0,F0);
}

// round 5
// speedup vs baseline: 1.7249x; 1.7249x over previous
#include <cuda_runtime.h>
#include <math.h>
#include <float.h>

#define B 8
#define SEQ 12
#define NN 1000
#define E 16000
#define HID 128
#define HEADS 8
#define DH 16
#define M_ROWS (B*NN)          /* 8000 */

// ---------------- static device scratch ----------------
__device__ float g_hin[(size_t)SEQ*B*NN*HID];   // [SEQ][B][N][HID]
__device__ float g_y  [(size_t)M_ROWS*HID];
__device__ float g_hp [(size_t)M_ROWS*HID];
__device__ float g_k1 [(size_t)M_ROWS*HID];
__device__ float g_k2 [(size_t)M_ROWS*HID];
__device__ float g_k3 [(size_t)M_ROWS*HID];
__device__ float g_tmp[(size_t)M_ROWS*HID];
__device__ float g_el [(size_t)M_ROWS*HEADS];
__device__ float g_er [(size_t)M_ROWS*HEADS];
__device__ int   g_cnt[NN];
__device__ int   g_cur[NN];
__device__ int   g_off[NN+1];
__device__ int   g_eidx[E];

// ---------------- fused init: inproj + y=h[:,0] + CSR zero ----------------
__global__ void k_init(const float* __restrict__ inp, const float* __restrict__ w_in,
                       const float* __restrict__ b_in, float* __restrict__ hin,
                       float* __restrict__ y, int* cnt, int* cur){
    int row = blockIdx.x;                 // over B*SEQ*NN (input order [B][SEQ][N])
    int t = threadIdx.x;
    if (blockIdx.x < 8){
        int q = blockIdx.x*128 + t;
        if (q < NN){ cnt[q] = 0; cur[q] = 0; }
    }
    int b = row / (SEQ*NN);
    int s = (row / NN) % SEQ;
    int n = row % NN;
    float x0 = inp[(size_t)row*2 + 0];
    float x1 = inp[(size_t)row*2 + 1];
    float v = fmaf(x0, w_in[t], fmaf(x1, w_in[HID+t], b_in[t]));
    hin[(((size_t)s*B + b)*NN + n)*HID + t] = v;
    if (s == 0) y[((size_t)b*NN + n)*HID + t] = v;
}

// ---------------- CSR construction (deterministic: per-node sorted edge ids) ----
__global__ void k_csr_count(const int* __restrict__ dst, int* cnt){
    int e = blockIdx.x*blockDim.x + threadIdx.x;
    if (e < E) atomicAdd(&cnt[dst[e]], 1);
}
__global__ void k_csr_scan(const int* __restrict__ cnt, int* off){
    __shared__ int s[1024];
    int t = threadIdx.x;
    s[t] = (t < NN) ? cnt[t] : 0;
    __syncthreads();
    #pragma unroll
    for (int o = 1; o < 1024; o <<= 1){
        int v = (t >= o) ? s[t-o] : 0;
        __syncthreads();
        s[t] += v;
        __syncthreads();
    }
    if (t == 0) off[0] = 0;
    if (t < NN) off[t+1] = s[t];
}
__global__ void k_csr_fill(const int* __restrict__ dst, const int* __restrict__ off,
                           int* cur, int* eidx){
    int e = blockIdx.x*blockDim.x + threadIdx.x;
    if (e < E){
        int d = dst[e];
        int p = atomicAdd(&cur[d], 1);
        eidx[off[d] + p] = e;
    }
}
__global__ void k_csr_sort(const int* __restrict__ off, int* eidx){
    if (threadIdx.x != 0) return;
    int n = blockIdx.x;
    int a = off[n], b = off[n+1];
    for (int i = a+1; i < b; i++){
        int v = eidx[i]; int j = i-1;
        while (j >= a && eidx[j] > v){ eidx[j+1] = eidx[j]; j--; }
        eidx[j+1] = v;
    }
}

// ---------------- GEMM: C = act( (A0 + c1*A1)@W0 [+ A2@W1] + b0 + b1 ) --------
// Optional epilogue: el/er per-(row,head) attention logit partials (GAT path).
// M=8000, K=N=128. grid (125,2), 256 threads, 4x4 micro-tile per thread.
__global__ void __launch_bounds__(256) k_gemm(
    const float* __restrict__ A0, const float* __restrict__ A1, float c1,
    const float* __restrict__ W0,
    const float* __restrict__ A2, const float* __restrict__ W1,
    const float* __restrict__ b0, const float* __restrict__ b1,
    float* __restrict__ C, int act,
    float* __restrict__ el, float* __restrict__ er,
    const float* __restrict__ a_l, const float* __restrict__ a_r)
{
    __shared__ float sA[64][132];          // padded: bank-clean float4 reads
    int row0    = blockIdx.x * 64;
    int colBase = blockIdx.y * 64;
    int tid = threadIdx.x;
    int tx = tid & 15, ty = tid >> 4;      // tx: col groups, ty: row groups
    int col0 = colBase + tx*4;

    float acc[4][4];
    #pragma unroll
    for (int i=0;i<4;i++)
        #pragma unroll
        for (int j=0;j<4;j++) acc[i][j] = 0.f;

    // ---- load A tile (with fused axpy) ----
    {
        const float4* A04 = (const float4*)A0;
        const float4* A14 = (const float4*)A1;
        for (int i = tid; i < 64*32; i += 256){
            int r = i >> 5, c4 = i & 31;
            float4 v = A04[(size_t)(row0+r)*32 + c4];
            if (A1){
                float4 u = A14[(size_t)(row0+r)*32 + c4];
                v.x = fmaf(c1,u.x,v.x); v.y = fmaf(c1,u.y,v.y);
                v.z = fmaf(c1,u.z,v.z); v.w = fmaf(c1,u.w,v.w);
            }
            *reinterpret_cast<float4*>(&sA[r][c4*4]) = v;
        }
    }
    __syncthreads();
    // ---- product 0 ----
    {
        const float* Wp = W0 + col0;
        #pragma unroll 2
        for (int k = 0; k < HID; k += 4){
            float a[4][4];
            #pragma unroll
            for (int i=0;i<4;i++)
                *reinterpret_cast<float4*>(&a[i][0]) =
                    *reinterpret_cast<const float4*>(&sA[ty*4+i][k]);
            #pragma unroll
            for (int kk=0; kk<4; kk++){
                float4 w = *reinterpret_cast<const float4*>(Wp + (size_t)(k+kk)*HID);
                #pragma unroll
                for (int i=0;i<4;i++){
                    acc[i][0] = fmaf(a[i][kk], w.x, acc[i][0]);
                    acc[i][1] = fmaf(a[i][kk], w.y, acc[i][1]);
                    acc[i][2] = fmaf(a[i][kk], w.z, acc[i][2]);
                    acc[i][3] = fmaf(a[i][kk], w.w, acc[i][3]);
                }
            }
        }
    }
    // ---- optional product 1 ----
    if (A2){
        __syncthreads();
        const float4* A24 = (const float4*)A2;
        for (int i = tid; i < 64*32; i += 256){
            int r = i >> 5, c4 = i & 31;
            *reinterpret_cast<float4*>(&sA[r][c4*4]) = A24[(size_t)(row0+r)*32 + c4];
        }
        __syncthreads();
        const float* Wp = W1 + col0;
        #pragma unroll 2
        for (int k = 0; k < HID; k += 4){
            float a[4][4];
            #pragma unroll
            for (int i=0;i<4;i++)
                *reinterpret_cast<float4*>(&a[i][0]) =
                    *reinterpret_cast<const float4*>(&sA[ty*4+i][k]);
            #pragma unroll
            for (int kk=0; kk<4; kk++){
                float4 w = *reinterpret_cast<const float4*>(Wp + (size_t)(k+kk)*HID);
                #pragma unroll
                for (int i=0;i<4;i++){
                    acc[i][0] = fmaf(a[i][kk], w.x, acc[i][0]);
                    acc[i][1] = fmaf(a[i][kk], w.y, acc[i][1]);
                    acc[i][2] = fmaf(a[i][kk], w.z, acc[i][2]);
                    acc[i][3] = fmaf(a[i][kk], w.w, acc[i][3]);
                }
            }
        }
    }
    // ---- bias + activation + store ----
    float bias[4] = {0.f,0.f,0.f,0.f};
    if (b0){
        #pragma unroll
        for (int j=0;j<4;j++) bias[j] += b0[col0+j];
    }
    if (b1){
        #pragma unroll
        for (int j=0;j<4;j++) bias[j] += b1[col0+j];
    }
    #pragma unroll
    for (int i=0;i<4;i++){
        #pragma unroll
        for (int j=0;j<4;j++) acc[i][j] += bias[j];
    }
    #pragma unroll
    for (int i=0;i<4;i++){
        int r = row0 + ty*4 + i;
        float4 o;
        o.x = acc[i][0]; o.y = acc[i][1]; o.z = acc[i][2]; o.w = acc[i][3];
        if (act){ o.x=tanhf(o.x); o.y=tanhf(o.y); o.z=tanhf(o.z); o.w=tanhf(o.w); }
        *reinterpret_cast<float4*>(C + (size_t)r*HID + col0) = o;
    }
    // ---- GAT logit epilogue: el/er[row][head] (each 64-col block owns 4 heads) ----
    if (el){
        int head = (colBase >> 4) + (tx >> 2);
        int dbase = (tx & 3) * 4;                    // offset within head's 16 dims
        #pragma unroll
        for (int i=0;i<4;i++){
            float pl = 0.f, pr = 0.f;
            #pragma unroll
            for (int j=0;j<4;j++){
                pl = fmaf(acc[i][j], a_l[head*DH + dbase + j], pl);
                pr = fmaf(acc[i][j], a_r[head*DH + dbase + j], pr);
            }
            pl += __shfl_xor_sync(0xffffffffu, pl, 1);
            pl += __shfl_xor_sync(0xffffffffu, pl, 2);
            pr += __shfl_xor_sync(0xffffffffu, pr, 1);
            pr += __shfl_xor_sync(0xffffffffu, pr, 2);
            if ((tx & 3) == 0){
                int r = row0 + ty*4 + i;
                el[(size_t)r*HEADS + head] = pl;
                er[(size_t)r*HEADS + head] = pr;
            }
        }
    }
}

// ---------------- GAT: warp-per-(node,batch); no block barriers ----------------
// grid = NN blocks, 256 threads: warp w = batch w, all 8 batches of node blockIdx.x.
// lane handles dims {lane, lane+32, lane+64, lane+96}; head(dim)=dim>>4.
__global__ void __launch_bounds__(256) k_gat(
    const float* __restrict__ hp, const float* __restrict__ el,
    const float* __restrict__ er,
    const int* __restrict__ off, const int* __restrict__ eidx,
    const int* __restrict__ src, float* __restrict__ kout,
    const float* __restrict__ yin, const float* __restrict__ k1,
    const float* __restrict__ k2, const float* __restrict__ k3, float dtc)
{
    const unsigned FULL = 0xffffffffu;
    int n    = blockIdx.x;
    int b    = threadIdx.x >> 5;
    int lane = threadIdx.x & 31;
    int bn   = b*NN + n;

    const float* hb  = hp + (size_t)b*NN*HID;
    const float* elb = el + (size_t)b*NN*HEADS;

    // er for this destination node (all heads; broadcast 32B load)
    float erv[8];
    {
        float4 e0v = *reinterpret_cast<const float4*>(er + (size_t)bn*HEADS);
        float4 e1v = *reinterpret_cast<const float4*>(er + (size_t)bn*HEADS + 4);
        erv[0]=e0v.x; erv[1]=e0v.y; erv[2]=e0v.z; erv[3]=e0v.w;
        erv[4]=e1v.x; erv[5]=e1v.y; erv[6]=e1v.z; erv[7]=e1v.w;
    }

    int e0 = off[n], deg = off[n+1] - e0;

    float acc[4] = {0.f,0.f,0.f,0.f};
    float m[8], ssum[8];
    #pragma unroll
    for (int h=0;h<8;h++){ m[h] = -FLT_MAX; ssum[h] = 0.f; }

    for (int base = 0; base < deg; base += 32){
        int cnt = min(32, deg - base);
        int sj = 0;
        float lg[8];
        if (lane < cnt){
            sj = src[eidx[e0 + base + lane]];
            float4 v0 = *reinterpret_cast<const float4*>(elb + (size_t)sj*HEADS);
            float4 v1 = *reinterpret_cast<const float4*>(elb + (size_t)sj*HEADS + 4);
            float t0;
            t0 = v0.x + erv[0]; lg[0] = (t0>=0.f)?t0:0.2f*t0;
            t0 = v0.y + erv[1]; lg[1] = (t0>=0.f)?t0:0.2f*t0;
            t0 = v0.z + erv[2]; lg[2] = (t0>=0.f)?t0:0.2f*t0;
            t0 = v0.w + erv[3]; lg[3] = (t0>=0.f)?t0:0.2f*t0;
            t0 = v1.x + erv[4]; lg[4] = (t0>=0.f)?t0:0.2f*t0;
            t0 = v1.y + erv[5]; lg[5] = (t0>=0.f)?t0:0.2f*t0;
            t0 = v1.z + erv[6]; lg[6] = (t0>=0.f)?t0:0.2f*t0;
            t0 = v1.w + erv[7]; lg[7] = (t0>=0.f)?t0:0.2f*t0;
        } else {
            #pragma unroll
            for (int h=0;h<8;h++) lg[h] = -FLT_MAX;
        }
        // warp max per head
        float nm[8];
        #pragma unroll
        for (int h=0;h<8;h++) nm[h] = lg[h];
        #pragma unroll
        for (int o = 16; o > 0; o >>= 1){
            #pragma unroll
            for (int h=0;h<8;h++)
                nm[h] = fmaxf(nm[h], __shfl_xor_sync(FULL, nm[h], o));
        }
        // online-softmax merge
        float w[8], sc[8];
        #pragma unroll
        for (int h=0;h<8;h++){
            float newm = fmaxf(m[h], nm[h]);
            sc[h] = (m[h] == -FLT_MAX) ? 0.f : __expf(m[h] - newm);
            m[h]  = newm;
            w[h]  = __expf(lg[h] - newm);     // 0 for invalid lanes
        }
        if (base > 0){
            #pragma unroll
            for (int g=0;g<4;g++){
                float s01 = (lane < 16) ? sc[2*g] : sc[2*g+1];
                acc[g] *= s01;
            }
            #pragma unroll
            for (int h=0;h<8;h++) ssum[h] *= sc[h];
        }
        // chunk weight sums
        float cs[8];
        #pragma unroll
        for (int h=0;h<8;h++) cs[h] = w[h];
        #pragma unroll
        for (int o = 16; o > 0; o >>= 1){
            #pragma unroll
            for (int h=0;h<8;h++)
                cs[h] += __shfl_xor_sync(FULL, cs[h], o);
        }
        #pragma unroll
        for (int h=0;h<8;h++) ssum[h] += cs[h];
        // aggregation
        for (int j = 0; j < cnt; j++){
            int s = __shfl_sync(FULL, sj, j);
            const float* hr = hb + (size_t)s*HID;
            #pragma unroll
            for (int g=0;g<4;g++){
                float wa = __shfl_sync(FULL, w[2*g],   j);
                float wb = __shfl_sync(FULL, w[2*g+1], j);
                float ww = (lane < 16) ? wa : wb;
                acc[g] = fmaf(ww, hr[lane + 32*g], acc[g]);
            }
        }
    }
    #pragma unroll
    for (int g=0;g<4;g++){
        float s = ((lane < 16) ? ssum[2*g] : ssum[2*g+1]) + 1e-16f;
        float kv = acc[g] / s;
        size_t o = (size_t)bn*HID + lane + 32*g;
        if (yin){
            kout[o] = yin[o] + dtc*(k1[o] + 2.f*k2[o] + 2.f*k3[o] + kv);
        } else {
            kout[o] = kv;
        }
    }
}

// ---------------- LayerNorm over last dim (128) ----------------
__global__ void __launch_bounds__(128) k_ln(const float* __restrict__ s, float* __restrict__ d){
    int row = blockIdx.x;
    int t = threadIdx.x;
    __shared__ float sh[4];
    float v = s[(size_t)row*HID + t];

    float a = v;
    #pragma unroll
    for (int o = 16; o > 0; o >>= 1) a += __shfl_xor_sync(0xffffffffu, a, o);
    if ((t & 31) == 0) sh[t >> 5] = a;
    __syncthreads();
    float mean = (sh[0]+sh[1]+sh[2]+sh[3]) * (1.f/HID);

    float dv = v - mean;
    float q = dv*dv;
    __syncthreads();
    #pragma unroll
    for (int o = 16; o > 0; o >>= 1) q += __shfl_xor_sync(0xffffffffu, q, o);
    if ((t & 31) == 0) sh[t >> 5] = q;
    __syncthreads();
    float var = (sh[0]+sh[1]+sh[2]+sh[3]) * (1.f/HID);

    d[(size_t)row*HID + t] = dv / sqrtf(var + 1e-5f);
}

// ---------------- launch ----------------
extern "C" void kernel_launch(void* const* d_in, const int* in_sizes, int n_in,
                              void* d_out, int out_size)
{
    const float* inputs = (const float*)d_in[0];
    const int*   src    = (const int*)  d_in[1];
    const int*   dst    = (const int*)  d_in[2];
    const float* w_in   = (const float*)d_in[3];
    const float* b_in   = (const float*)d_in[4];
    const float* w_gat  = (const float*)d_in[5];
    const float* a_l    = (const float*)d_in[6];
    const float* a_r    = (const float*)d_in[7];
    const float* w_W    = (const float*)d_in[8];
    const float* b_W    = (const float*)d_in[9];
    const float* w_U    = (const float*)d_in[10];
    const float* b_U    = (const float*)d_in[11];
    const float* w_o1   = (const float*)d_in[12];
    const float* b_o1   = (const float*)d_in[13];
    const float* w_o2   = (const float*)d_in[14];
    const float* b_o2   = (const float*)d_in[15];
    float* out = (float*)d_out;

    float *hin, *y, *hp, *k1, *k2, *k3, *tmp, *el, *er;
    int *cnt, *cur, *off, *eidx;
    cudaGetSymbolAddress((void**)&hin, g_hin);
    cudaGetSymbolAddress((void**)&y,   g_y);
    cudaGetSymbolAddress((void**)&hp,  g_hp);
    cudaGetSymbolAddress((void**)&k1,  g_k1);
    cudaGetSymbolAddress((void**)&k2,  g_k2);
    cudaGetSymbolAddress((void**)&k3,  g_k3);
    cudaGetSymbolAddress((void**)&tmp, g_tmp);
    cudaGetSymbolAddress((void**)&el,  g_el);
    cudaGetSymbolAddress((void**)&er,  g_er);
    cudaGetSymbolAddress((void**)&cnt, g_cnt);
    cudaGetSymbolAddress((void**)&cur, g_cur);
    cudaGetSymbolAddress((void**)&off, g_off);
    cudaGetSymbolAddress((void**)&eidx,g_eidx);

    const float* F0 = (const float*)0;
    float*       FW = (float*)0;

    dim3 gg(125, 2);
    const float dt  = 0.25f;
    const float dtc = dt / 6.0f;

    // prelude ordered so the first k_gemm is at launch index 4 (ncu -s 5 capture)
    k_init     <<<B*SEQ*NN, HID>>>(inputs, w_in, b_in, hin, y, cnt, cur);
    k_csr_count<<<(E+255)/256, 256>>>(dst, cnt);
    k_csr_scan <<<1, 1024>>>(cnt, off);

    // first RK4 stage-1 GEMM (does not need CSR)
    k_gemm<<<gg,256>>>(y, F0, 0.f, w_gat, F0,F0,F0,F0, hp, 0, el, er, a_l, a_r);

    k_csr_fill <<<(E+255)/256, 256>>>(dst, off, cur, eidx);
    k_csr_sort <<<NN, 32>>>(off, eidx);

    for (int idx = 0; idx < SEQ; idx++){
        for (int s = 0; s < 4; s++){
            if (!(idx == 0 && s == 0)){
                k_gemm<<<gg,256>>>(y, F0, 0.f, w_gat, F0,F0,F0,F0, hp, 0, el, er, a_l, a_r);
            }
            k_gat <<<NN,256>>>(hp, el, er, off, eidx, src, k1, F0,F0,F0,F0, 0.f);
            k_gemm<<<gg,256>>>(y, k1, 0.5f*dt, w_gat, F0,F0,F0,F0, hp, 0, el, er, a_l, a_r);
            k_gat <<<NN,256>>>(hp, el, er, off, eidx, src, k2, F0,F0,F0,F0, 0.f);
            k_gemm<<<gg,256>>>(y, k2, 0.5f*dt, w_gat, F0,F0,F0,F0, hp, 0, el, er, a_l, a_r);
            k_gat <<<NN,256>>>(hp, el, er, off, eidx, src, k3, F0,F0,F0,F0, 0.f);
            k_gemm<<<gg,256>>>(y, k3, dt, w_gat, F0,F0,F0,F0, hp, 0, el, er, a_l, a_r);
            k_gat <<<NN,256>>>(hp, el, er, off, eidx, src, y, y, k1, k2, k3, dtc);
        }
        if (idx > 0){
            const float* hidx = hin + (size_t)idx * M_ROWS * HID;
            k_gemm<<<gg,256>>>(y, F0, 0.f, w_W, hidx, w_U, b_W, b_U, tmp, 1, FW,FW,F0,F0);
            k_ln  <<<M_ROWS,128>>>(tmp, y);
        } else {
            k_ln  <<<M_ROWS,128>>>(y, y);
        }
    }

    // out = tanh(y@w_o1 + b_o1) @ w_o2 + b_o2
    k_gemm<<<gg,256>>>(y,   F0, 0.f, w_o1, F0,F0, b_o1,F0, tmp, 1, FW,FW,F0,F0);
    k_gemm<<<gg,256>>>(tmp, F0, 0.f, w_o2, F0,F0, b_o2,F0, out, 0, FW,FW,F0,F0);
}

// round 6
// speedup vs baseline: 1.7868x; 1.0359x over previous
#include <cuda_runtime.h>
#include <math.h>
#include <float.h>

#define B 8
#define SEQ 12
#define NN 1000
#define E 16000
#define HID 128
#define HEADS 8
#define DH 16
#define M_ROWS (B*NN)          /* 8000 */

#define AT_STRIDE 68           /* 64 rows + 4 pad (floats); 272B = 16B-aligned per k */
#define GEMM_SMEM (HID*HID*4 + HID*AT_STRIDE*4)   /* 64KB W + 34KB A^T = 100352B */

// ---------------- static device scratch ----------------
__device__ float g_hin[(size_t)SEQ*B*NN*HID];   // [SEQ][B][N][HID]
__device__ float g_y  [(size_t)M_ROWS*HID];
__device__ float g_hp [(size_t)M_ROWS*HID];
__device__ float g_k1 [(size_t)M_ROWS*HID];
__device__ float g_k2 [(size_t)M_ROWS*HID];
__device__ float g_k3 [(size_t)M_ROWS*HID];
__device__ float g_tmp[(size_t)M_ROWS*HID];
__device__ float g_el [(size_t)M_ROWS*HEADS];
__device__ float g_er [(size_t)M_ROWS*HEADS];
__device__ int   g_cnt[NN];
__device__ int   g_cur[NN];
__device__ int   g_off[NN+1];
__device__ int   g_eidx[E];

// ---------------- fused init: inproj + y=h[:,0] + CSR zero ----------------
__global__ void k_init(const float* __restrict__ inp, const float* __restrict__ w_in,
                       const float* __restrict__ b_in, float* __restrict__ hin,
                       float* __restrict__ y, int* cnt, int* cur){
    int row = blockIdx.x;                 // over B*SEQ*NN (input order [B][SEQ][N])
    int t = threadIdx.x;
    if (blockIdx.x < 8){
        int q = blockIdx.x*128 + t;
        if (q < NN){ cnt[q] = 0; cur[q] = 0; }
    }
    int b = row / (SEQ*NN);
    int s = (row / NN) % SEQ;
    int n = row % NN;
    float x0 = inp[(size_t)row*2 + 0];
    float x1 = inp[(size_t)row*2 + 1];
    float v = fmaf(x0, w_in[t], fmaf(x1, w_in[HID+t], b_in[t]));
    hin[(((size_t)s*B + b)*NN + n)*HID + t] = v;
    if (s == 0) y[((size_t)b*NN + n)*HID + t] = v;
}

// ---------------- CSR construction (deterministic: per-node sorted edge ids) ----
__global__ void k_csr_count(const int* __restrict__ dst, int* cnt){
    int e = blockIdx.x*blockDim.x + threadIdx.x;
    if (e < E) atomicAdd(&cnt[dst[e]], 1);
}
__global__ void k_csr_scan(const int* __restrict__ cnt, int* off){
    __shared__ int s[1024];
    int t = threadIdx.x;
    s[t] = (t < NN) ? cnt[t] : 0;
    __syncthreads();
    #pragma unroll
    for (int o = 1; o < 1024; o <<= 1){
        int v = (t >= o) ? s[t-o] : 0;
        __syncthreads();
        s[t] += v;
        __syncthreads();
    }
    if (t == 0) off[0] = 0;
    if (t < NN) off[t+1] = s[t];
}
__global__ void k_csr_fill(const int* __restrict__ dst, const int* __restrict__ off,
                           int* cur, int* eidx){
    int e = blockIdx.x*blockDim.x + threadIdx.x;
    if (e < E){
        int d = dst[e];
        int p = atomicAdd(&cur[d], 1);
        eidx[off[d] + p] = e;
    }
}
__global__ void k_csr_sort(const int* __restrict__ off, int* eidx){
    if (threadIdx.x != 0) return;
    int n = blockIdx.x;
    int a = off[n], b = off[n+1];
    for (int i = a+1; i < b; i++){
        int v = eidx[i]; int j = i-1;
        while (j >= a && eidx[j] > v){ eidx[j+1] = eidx[j]; j--; }
        eidx[j+1] = v;
    }
}

// ---------------- GEMM: C = act( (A0 + c1*A1)@W0 [+ A2@W1] + b0 + b1 ) --------
// 64 rows x 128 cols per block, grid 125 (single wave), 256 threads.
// W staged in smem (64KB); A staged TRANSPOSED (sAT[k][row], 34KB) so the inner
// loop is pure LDS: per k per thread 1x float4 W + 2x float4 A(broadcast) + 32 FFMA.
// Optional epilogue: el/er per-(row,head) GAT logits (head = tx>>2).
__global__ void __launch_bounds__(256) k_gemm(
    const float* __restrict__ A0, const float* __restrict__ A1, float c1,
    const float* __restrict__ W0,
    const float* __restrict__ A2, const float* __restrict__ W1,
    const float* __restrict__ b0, const float* __restrict__ b1,
    float* __restrict__ C, int act,
    float* __restrict__ el, float* __restrict__ er,
    const float* __restrict__ a_l, const float* __restrict__ a_r)
{
    extern __shared__ float smem[];
    float* sW  = smem;                 // [128][128]
    float* sAT = smem + HID*HID;       // [128][AT_STRIDE]

    int row0 = blockIdx.x * 64;
    int tid = threadIdx.x;
    int tx = tid & 31, ty = tid >> 5;  // tx: 4 cols each; ty: 8 rows each
    int col0 = tx * 4;

    float acc[8][4];
    #pragma unroll
    for (int i=0;i<8;i++)
        #pragma unroll
        for (int j=0;j<4;j++) acc[i][j] = 0.f;

    // ---- stage W0 (64KB) ----
    {
        const float4* W4 = (const float4*)W0;
        float4* sW4 = (float4*)sW;
        #pragma unroll
        for (int i = tid; i < HID*32; i += 256) sW4[i] = W4[i];
    }
    // ---- stage A tile transposed (with fused axpy) ----
    {
        const float4* A04 = (const float4*)A0;
        const float4* A14 = (const float4*)A1;
        for (int i = tid; i < 64*32; i += 256){
            int r = i >> 5, c4 = i & 31;
            float4 v = A04[(size_t)(row0+r)*32 + c4];
            if (A1){
                float4 u = A14[(size_t)(row0+r)*32 + c4];
                v.x = fmaf(c1,u.x,v.x); v.y = fmaf(c1,u.y,v.y);
                v.z = fmaf(c1,u.z,v.z); v.w = fmaf(c1,u.w,v.w);
            }
            int k0 = c4*4;
            sAT[(k0+0)*AT_STRIDE + r] = v.x;
            sAT[(k0+1)*AT_STRIDE + r] = v.y;
            sAT[(k0+2)*AT_STRIDE + r] = v.z;
            sAT[(k0+3)*AT_STRIDE + r] = v.w;
        }
    }
    __syncthreads();
    // ---- product 0 (all-smem inner loop) ----
    {
        const float4* sW4 = (const float4*)sW;
        #pragma unroll 4
        for (int k = 0; k < HID; k++){
            float4 w = sW4[k*32 + tx];
            const float* ak = sAT + k*AT_STRIDE + ty*8;
            float4 a0 = *reinterpret_cast<const float4*>(ak);
            float4 a1 = *reinterpret_cast<const float4*>(ak + 4);
            float av[8] = {a0.x,a0.y,a0.z,a0.w,a1.x,a1.y,a1.z,a1.w};
            #pragma unroll
            for (int i=0;i<8;i++){
                acc[i][0] = fmaf(av[i], w.x, acc[i][0]);
                acc[i][1] = fmaf(av[i], w.y, acc[i][1]);
                acc[i][2] = fmaf(av[i], w.z, acc[i][2]);
                acc[i][3] = fmaf(av[i], w.w, acc[i][3]);
            }
        }
    }
    // ---- optional product 1 ----
    if (A2){
        __syncthreads();
        {
            const float4* W4 = (const float4*)W1;
            float4* sW4 = (float4*)sW;
            #pragma unroll
            for (int i = tid; i < HID*32; i += 256) sW4[i] = W4[i];
            const float4* A24 = (const float4*)A2;
            for (int i = tid; i < 64*32; i += 256){
                int r = i >> 5, c4 = i & 31;
                float4 v = A24[(size_t)(row0+r)*32 + c4];
                int k0 = c4*4;
                sAT[(k0+0)*AT_STRIDE + r] = v.x;
                sAT[(k0+1)*AT_STRIDE + r] = v.y;
                sAT[(k0+2)*AT_STRIDE + r] = v.z;
                sAT[(k0+3)*AT_STRIDE + r] = v.w;
            }
        }
        __syncthreads();
        const float4* sW4 = (const float4*)sW;
        #pragma unroll 4
        for (int k = 0; k < HID; k++){
            float4 w = sW4[k*32 + tx];
            const float* ak = sAT + k*AT_STRIDE + ty*8;
            float4 a0 = *reinterpret_cast<const float4*>(ak);
            float4 a1 = *reinterpret_cast<const float4*>(ak + 4);
            float av[8] = {a0.x,a0.y,a0.z,a0.w,a1.x,a1.y,a1.z,a1.w};
            #pragma unroll
            for (int i=0;i<8;i++){
                acc[i][0] = fmaf(av[i], w.x, acc[i][0]);
                acc[i][1] = fmaf(av[i], w.y, acc[i][1]);
                acc[i][2] = fmaf(av[i], w.z, acc[i][2]);
                acc[i][3] = fmaf(av[i], w.w, acc[i][3]);
            }
        }
    }
    // ---- bias + activation + store ----
    float bias[4] = {0.f,0.f,0.f,0.f};
    if (b0){
        #pragma unroll
        for (int j=0;j<4;j++) bias[j] += b0[col0+j];
    }
    if (b1){
        #pragma unroll
        for (int j=0;j<4;j++) bias[j] += b1[col0+j];
    }
    #pragma unroll
    for (int i=0;i<8;i++){
        #pragma unroll
        for (int j=0;j<4;j++) acc[i][j] += bias[j];
    }
    #pragma unroll
    for (int i=0;i<8;i++){
        int r = row0 + ty*8 + i;
        float4 o;
        o.x = acc[i][0]; o.y = acc[i][1]; o.z = acc[i][2]; o.w = acc[i][3];
        if (act){ o.x=tanhf(o.x); o.y=tanhf(o.y); o.z=tanhf(o.z); o.w=tanhf(o.w); }
        *reinterpret_cast<float4*>(C + (size_t)r*HID + col0) = o;
    }
    // ---- GAT logit epilogue: el/er[row][head]; head = tx>>2 ----
    if (el){
        int head  = tx >> 2;
        int dbase = (tx & 3) * 4;
        #pragma unroll
        for (int i=0;i<8;i++){
            float pl = 0.f, pr = 0.f;
            #pragma unroll
            for (int j=0;j<4;j++){
                pl = fmaf(acc[i][j], a_l[head*DH + dbase + j], pl);
                pr = fmaf(acc[i][j], a_r[head*DH + dbase + j], pr);
            }
            pl += __shfl_xor_sync(0xffffffffu, pl, 1);
            pl += __shfl_xor_sync(0xffffffffu, pl, 2);
            pr += __shfl_xor_sync(0xffffffffu, pr, 1);
            pr += __shfl_xor_sync(0xffffffffu, pr, 2);
            if ((tx & 3) == 0){
                int r = row0 + ty*8 + i;
                el[(size_t)r*HEADS + head] = pl;
                er[(size_t)r*HEADS + head] = pr;
            }
        }
    }
}

// ---------------- GAT: warp-per-(node,batch); no block barriers ----------------
__global__ void __launch_bounds__(256) k_gat(
    const float* __restrict__ hp, const float* __restrict__ el,
    const float* __restrict__ er,
    const int* __restrict__ off, const int* __restrict__ eidx,
    const int* __restrict__ src, float* __restrict__ kout,
    const float* __restrict__ yin, const float* __restrict__ k1,
    const float* __restrict__ k2, const float* __restrict__ k3, float dtc)
{
    const unsigned FULL = 0xffffffffu;
    int n    = blockIdx.x;
    int b    = threadIdx.x >> 5;
    int lane = threadIdx.x & 31;
    int bn   = b*NN + n;

    const float* hb  = hp + (size_t)b*NN*HID;
    const float* elb = el + (size_t)b*NN*HEADS;

    float erv[8];
    {
        float4 e0v = *reinterpret_cast<const float4*>(er + (size_t)bn*HEADS);
        float4 e1v = *reinterpret_cast<const float4*>(er + (size_t)bn*HEADS + 4);
        erv[0]=e0v.x; erv[1]=e0v.y; erv[2]=e0v.z; erv[3]=e0v.w;
        erv[4]=e1v.x; erv[5]=e1v.y; erv[6]=e1v.z; erv[7]=e1v.w;
    }

    int e0 = off[n], deg = off[n+1] - e0;

    float acc[4] = {0.f,0.f,0.f,0.f};
    float m[8], ssum[8];
    #pragma unroll
    for (int h=0;h<8;h++){ m[h] = -FLT_MAX; ssum[h] = 0.f; }

    for (int base = 0; base < deg; base += 32){
        int cnt = min(32, deg - base);
        int sj = 0;
        float lg[8];
        if (lane < cnt){
            sj = src[eidx[e0 + base + lane]];
            float4 v0 = *reinterpret_cast<const float4*>(elb + (size_t)sj*HEADS);
            float4 v1 = *reinterpret_cast<const float4*>(elb + (size_t)sj*HEADS + 4);
            float t0;
            t0 = v0.x + erv[0]; lg[0] = (t0>=0.f)?t0:0.2f*t0;
            t0 = v0.y + erv[1]; lg[1] = (t0>=0.f)?t0:0.2f*t0;
            t0 = v0.z + erv[2]; lg[2] = (t0>=0.f)?t0:0.2f*t0;
            t0 = v0.w + erv[3]; lg[3] = (t0>=0.f)?t0:0.2f*t0;
            t0 = v1.x + erv[4]; lg[4] = (t0>=0.f)?t0:0.2f*t0;
            t0 = v1.y + erv[5]; lg[5] = (t0>=0.f)?t0:0.2f*t0;
            t0 = v1.z + erv[6]; lg[6] = (t0>=0.f)?t0:0.2f*t0;
            t0 = v1.w + erv[7]; lg[7] = (t0>=0.f)?t0:0.2f*t0;
        } else {
            #pragma unroll
            for (int h=0;h<8;h++) lg[h] = -FLT_MAX;
        }
        float nm[8];
        #pragma unroll
        for (int h=0;h<8;h++) nm[h] = lg[h];
        #pragma unroll
        for (int o = 16; o > 0; o >>= 1){
            #pragma unroll
            for (int h=0;h<8;h++)
                nm[h] = fmaxf(nm[h], __shfl_xor_sync(FULL, nm[h], o));
        }
        float w[8], sc[8];
        #pragma unroll
        for (int h=0;h<8;h++){
            float newm = fmaxf(m[h], nm[h]);
            sc[h] = (m[h] == -FLT_MAX) ? 0.f : __expf(m[h] - newm);
            m[h]  = newm;
            w[h]  = __expf(lg[h] - newm);
        }
        if (base > 0){
            #pragma unroll
            for (int g=0;g<4;g++){
                float s01 = (lane < 16) ? sc[2*g] : sc[2*g+1];
                acc[g] *= s01;
            }
            #pragma unroll
            for (int h=0;h<8;h++) ssum[h] *= sc[h];
        }
        float cs[8];
        #pragma unroll
        for (int h=0;h<8;h++) cs[h] = w[h];
        #pragma unroll
        for (int o = 16; o > 0; o >>= 1){
            #pragma unroll
            for (int h=0;h<8;h++)
                cs[h] += __shfl_xor_sync(FULL, cs[h], o);
        }
        #pragma unroll
        for (int h=0;h<8;h++) ssum[h] += cs[h];
        for (int j = 0; j < cnt; j++){
            int s = __shfl_sync(FULL, sj, j);
            const float* hr = hb + (size_t)s*HID;
            #pragma unroll
            for (int g=0;g<4;g++){
                float wa = __shfl_sync(FULL, w[2*g],   j);
                float wb = __shfl_sync(FULL, w[2*g+1], j);
                float ww = (lane < 16) ? wa : wb;
                acc[g] = fmaf(ww, hr[lane + 32*g], acc[g]);
            }
        }
    }
    #pragma unroll
    for (int g=0;g<4;g++){
        float s = ((lane < 16) ? ssum[2*g] : ssum[2*g+1]) + 1e-16f;
        float kv = acc[g] / s;
        size_t o = (size_t)bn*HID + lane + 32*g;
        if (yin){
            kout[o] = yin[o] + dtc*(k1[o] + 2.f*k2[o] + 2.f*k3[o] + kv);
        } else {
            kout[o] = kv;
        }
    }
}

// ---------------- LayerNorm over last dim (128) ----------------
__global__ void __launch_bounds__(128) k_ln(const float* __restrict__ s, float* __restrict__ d){
    int row = blockIdx.x;
    int t = threadIdx.x;
    __shared__ float sh[4];
    float v = s[(size_t)row*HID + t];

    float a = v;
    #pragma unroll
    for (int o = 16; o > 0; o >>= 1) a += __shfl_xor_sync(0xffffffffu, a, o);
    if ((t & 31) == 0) sh[t >> 5] = a;
    __syncthreads();
    float mean = (sh[0]+sh[1]+sh[2]+sh[3]) * (1.f/HID);

    float dv = v - mean;
    float q = dv*dv;
    __syncthreads();
    #pragma unroll
    for (int o = 16; o > 0; o >>= 1) q += __shfl_xor_sync(0xffffffffu, q, o);
    if ((t & 31) == 0) sh[t >> 5] = q;
    __syncthreads();
    float var = (sh[0]+sh[1]+sh[2]+sh[3]) * (1.f/HID);

    d[(size_t)row*HID + t] = dv / sqrtf(var + 1e-5f);
}

// ---------------- launch ----------------
extern "C" void kernel_launch(void* const* d_in, const int* in_sizes, int n_in,
                              void* d_out, int out_size)
{
    const float* inputs = (const float*)d_in[0];
    const int*   src    = (const int*)  d_in[1];
    const int*   dst    = (const int*)  d_in[2];
    const float* w_in   = (const float*)d_in[3];
    const float* b_in   = (const float*)d_in[4];
    const float* w_gat  = (const float*)d_in[5];
    const float* a_l    = (const float*)d_in[6];
    const float* a_r    = (const float*)d_in[7];
    const float* w_W    = (const float*)d_in[8];
    const float* b_W    = (const float*)d_in[9];
    const float* w_U    = (const float*)d_in[10];
    const float* b_U    = (const float*)d_in[11];
    const float* w_o1   = (const float*)d_in[12];
    const float* b_o1   = (const float*)d_in[13];
    const float* w_o2   = (const float*)d_in[14];
    const float* b_o2   = (const float*)d_in[15];
    float* out = (float*)d_out;

    float *hin, *y, *hp, *k1, *k2, *k3, *tmp, *el, *er;
    int *cnt, *cur, *off, *eidx;
    cudaGetSymbolAddress((void**)&hin, g_hin);
    cudaGetSymbolAddress((void**)&y,   g_y);
    cudaGetSymbolAddress((void**)&hp,  g_hp);
    cudaGetSymbolAddress((void**)&k1,  g_k1);
    cudaGetSymbolAddress((void**)&k2,  g_k2);
    cudaGetSymbolAddress((void**)&k3,  g_k3);
    cudaGetSymbolAddress((void**)&tmp, g_tmp);
    cudaGetSymbolAddress((void**)&el,  g_el);
    cudaGetSymbolAddress((void**)&er,  g_er);
    cudaGetSymbolAddress((void**)&cnt, g_cnt);
    cudaGetSymbolAddress((void**)&cur, g_cur);
    cudaGetSymbolAddress((void**)&off, g_off);
    cudaGetSymbolAddress((void**)&eidx,g_eidx);

    const float* F0 = (const float*)0;
    float*       FW = (float*)0;

    static bool attr_set = false;
    if (!attr_set){
        cudaFuncSetAttribute(k_gemm, cudaFuncAttributeMaxDynamicSharedMemorySize, GEMM_SMEM);
        attr_set = true;
    }

    const float dt  = 0.25f;
    const float dtc = dt / 6.0f;

    // prelude ordered so the first k_gemm is at launch index 4 (ncu -s 5 capture)
    k_init     <<<B*SEQ*NN, HID>>>(inputs, w_in, b_in, hin, y, cnt, cur);
    k_csr_count<<<(E+255)/256, 256>>>(dst, cnt);
    k_csr_scan <<<1, 1024>>>(cnt, off);

    // first RK4 stage-1 GEMM (does not need CSR)
    k_gemm<<<125,256,GEMM_SMEM>>>(y, F0, 0.f, w_gat, F0,F0,F0,F0, hp, 0, el, er, a_l, a_r);

    k_csr_fill <<<(E+255)/256, 256>>>(dst, off, cur, eidx);
    k_csr_sort <<<NN, 32>>>(off, eidx);

    for (int idx = 0; idx < SEQ; idx++){
        for (int s = 0; s < 4; s++){
            if (!(idx == 0 && s == 0)){
                k_gemm<<<125,256,GEMM_SMEM>>>(y, F0, 0.f, w_gat, F0,F0,F0,F0, hp, 0, el, er, a_l, a_r);
            }
            k_gat <<<NN,256>>>(hp, el, er, off, eidx, src, k1, F0,F0,F0,F0, 0.f);
            k_gemm<<<125,256,GEMM_SMEM>>>(y, k1, 0.5f*dt, w_gat, F0,F0,F0,F0, hp, 0, el, er, a_l, a_r);
            k_gat <<<NN,256>>>(hp, el, er, off, eidx, src, k2, F0,F0,F0,F0, 0.f);
            k_gemm<<<125,256,GEMM_SMEM>>>(y, k2, 0.5f*dt, w_gat, F0,F0,F0,F0, hp, 0, el, er, a_l, a_r);
            k_gat <<<NN,256>>>(hp, el, er, off, eidx, src, k3, F0,F0,F0,F0, 0.f);
            k_gemm<<<125,256,GEMM_SMEM>>>(y, k3, dt, w_gat, F0,F0,F0,F0, hp, 0, el, er, a_l, a_r);
            k_gat <<<NN,256>>>(hp, el, er, off, eidx, src, y, y, k1, k2, k3, dtc);
        }
        if (idx > 0){
            const float* hidx = hin + (size_t)idx * M_ROWS * HID;
            k_gemm<<<125,256,GEMM_SMEM>>>(y, F0, 0.f, w_W, hidx, w_U, b_W, b_U, tmp, 1, FW,FW,F0,F0);
            k_ln  <<<M_ROWS,128>>>(tmp, y);
        } else {
            k_ln  <<<M_ROWS,128>>>(y, y);
        }
    }

    // out = tanh(y@w_o1 + b_o1) @ w_o2 + b_o2
    k_gemm<<<125,256,GEMM_SMEM>>>(y,   F0, 0.f, w_o1, F0,F0, b_o1,F0, tmp, 1, FW,FW,F0,F0);
    k_gemm<<<125,256,GEMM_SMEM>>>(tmp, F0, 0.f, w_o2, F0,F0, b_o2,F0, out, 0, FW,FW,F0,F0);
}